// round 12
// baseline (speedup 1.0000x reference)
#include <cuda_runtime.h>
#include <cuda_bf16.h>
#include <cstdint>

#define T_STEPS 512
#define BATCH   8
#define HID     512
#define VOCAB   32000
#define CHUNK   32
#define NCHUNK  (T_STEPS / CHUNK)          // 16

#define NSCAN      (NCHUNK * BATCH * 2)    // 256 scan blocks
#define BID_L23    NSCAN                   // 256
#define BID_COMB0  (NSCAN + 1)             // 257
#define NCOMB      BATCH                   // 8
#define BID_FIN    (BID_COMB0 + NCOMB)     // 265: finalizer / fixup block
#define BID_STORE0 (BID_FIN + 1)           // 266
#define GRID_TOTAL 888                     // one wave @ occ 6 on >=148 SMs
#define NSTORECTA  (GRID_TOTAL - BID_STORE0) // 622 persistent store CTAs
#define NDET       (NCOMB + 1)

#define NROWS   (T_STEPS * BATCH)          // 4096 output rows
#define VCHUNKS 16                         // 2000 floats per chunk
#define NUNITS  (NROWS * VCHUNKS)          // 65536 store units (8000 B each)

// ---------------- device-global scratch (reset by finalizer each replay) ----
__device__ float    g_carry[NCHUNK * BATCH * HID];
__device__ float    g_locmax[NCHUNK * BATCH * HID];
__device__ int      g_mode23;
__device__ unsigned g_any3A[T_STEPS];
__device__ unsigned g_maskA[T_STEPS * 16];
__device__ unsigned g_any3B[T_STEPS * BATCH];
__device__ unsigned g_maskB[T_STEPS * BATCH * 16];
__device__ int      g_scan_done;
__device__ int      g_det_done;
__device__ int      g_flags;           // bit b: batch dirty; bit 8: mode23
__device__ int      g_store_done;

__device__ __forceinline__ float clip01(float b) { return fminf(fmaxf(b, 0.f), 1.f); }

__device__ __forceinline__ void spin_until(volatile int* p, int target) {
    while (*p < target) __nanosleep(128);
}

__device__ __forceinline__ float mask_sum(const unsigned* __restrict__ mp,
                                          const float* __restrict__ wrow)
{
    float a = 0.f;
#pragma unroll
    for (int k = 0; k < 16; k++) {
        unsigned m = mp[k];
        while (m) {
            int j = __ffs(m) - 1;
            m &= m - 1;
            a += wrow[32 * k + j];
        }
    }
    return a;
}

// ===========================================================================
__global__ void __launch_bounds__(256, 6) fused_snn(
    const int*   __restrict__ x,
    const float* __restrict__ emb,
    const float* __restrict__ pos,
    const float* __restrict__ beta1,
    const float* __restrict__ beta2,
    const float* __restrict__ beta3,
    const float* __restrict__ W2,
    const float* __restrict__ b2,
    const float* __restrict__ W3,
    const float* __restrict__ b3,
    const float* __restrict__ Wout,
    const float* __restrict__ bout,
    float*       __restrict__ out)
{
    const int bid = blockIdx.x;
    const int tid = threadIdx.x;

    // =================== persistent store CTAs: pure bout stream =============
    if (bid >= BID_STORE0) {
        const int sc   = bid - BID_STORE0;          // 0..621
        const int per  = NUNITS / NSTORECTA;        // 105
        const int rem  = NUNITS - per * NSTORECTA;  // 226
        const int u0   = sc * per + (sc < rem ? sc : rem);
        const int n    = per + (sc < rem ? 1 : 0);
        const bool has2 = tid < 244;                // 500 float4 per unit

        int ccur = -1;
        float4 r0 = make_float4(0.f, 0.f, 0.f, 0.f);
        float4 r1 = r0;

        // units ordered chunk-major: u = c*NROWS + row  -> a CTA's contiguous
        // run shares c (<=2 distinct c values), so bout regs rarely reload.
        for (int u = u0; u < u0 + n; u++) {
            const int c   = u >> 12;        // u / NROWS
            const int row = u & (NROWS - 1);
            if (c != ccur) {
                ccur = c;
                const int vbase = c * 2000;
                r0 = *reinterpret_cast<const float4*>(bout + vbase + tid * 4);
                if (has2)
                    r1 = *reinterpret_cast<const float4*>(bout + vbase + (tid + 256) * 4);
            }
            float* op = out + (size_t)row * VOCAB + ccur * 2000;
            __stcs(reinterpret_cast<float4*>(op + tid * 4), r0);
            if (has2)
                __stcs(reinterpret_cast<float4*>(op + (tid + 256) * 4), r1);
        }

        __threadfence();          // release: stores visible before count
        __syncthreads();
        if (tid == 0) atomicAdd(&g_store_done, 1);
        return;
    }

    // =================== scan blocks: layer-1 chunk locals ===================
    if (bid < NSCAN) {
        const int c    = bid >> 4;
        const int b    = (bid >> 1) & 7;
        const int half = bid & 1;
        const int h    = half * 256 + tid;
        const int t0   = c * CHUNK;

        __shared__ unsigned xoff[CHUNK];
        if (tid < CHUNK) xoff[tid] = (unsigned)x[(t0 + tid) * BATCH + b] * (unsigned)HID;
        __syncthreads();

        const float bt = clip01(beta1[h]);
        float loc = 0.f, lmax = -1e30f;
#pragma unroll 8
        for (int i = 0; i < CHUNK; i++) {
            const float e = emb[(size_t)xoff[i] + h];
            const float p = pos[(size_t)(t0 + i) * HID + h];
            loc = bt * loc + (e + p);
            lmax = fmaxf(lmax, loc);
        }
        const size_t idx = (size_t)(c * BATCH + b) * HID + h;
        g_carry[idx]  = loc;
        g_locmax[idx] = lmax;

        __threadfence();
        __syncthreads();
        if (tid == 0) atomicAdd(&g_scan_done, 1);
        return;
    }

    // =================== layers-2/3 block (independent) ======================
    if (bid == BID_L23) {
        float lim = 0.f;
        for (int h = tid; h < HID; h += 256) {
            float be2 = clip01(beta2[h]);
            float c2  = fmaxf(b2[h], 0.f);
            float g2  = (be2 >= 1.f) ? (float)T_STEPS
                                     : (1.f - powf(be2, (float)T_STEPS)) / (1.f - be2);
            float be3 = clip01(beta3[h]);
            float c3  = fmaxf(b3[h], 0.f);
            float g3  = (be3 >= 1.f) ? (float)T_STEPS
                                     : (1.f - powf(be3, (float)T_STEPS)) / (1.f - be3);
            lim = fmaxf(lim, fmaxf(c2 * g2, c3 * g3));
        }
        int risky = __syncthreads_or(lim >= 0.98f);
        if (tid == 0) {
            g_mode23 = risky;
            if (risky) atomicOr(&g_flags, 1 << 8);
        }

        if (risky && tid < 32) {
            // exact sequential sim of layers 2/3 with constant input relu(b2)
            __shared__ float spkSh[HID];
            const int lane = tid;
            float m2[16], m3[16], s2[16], s3[16];
            float bb2[16], bb3[16], rb2[16], rb3[16], b3raw[16];
#pragma unroll
            for (int k = 0; k < 16; k++) {
                int h = lane + 32 * k;
                m2[k] = m3[k] = s2[k] = s3[k] = 0.f;
                bb2[k] = clip01(beta2[h]); bb3[k] = clip01(beta3[h]);
                rb2[k] = fmaxf(b2[h], 0.f);
                b3raw[k] = b3[h];
                rb3[k] = fmaxf(b3raw[k], 0.f);
            }
            for (int t = 0; t < T_STEPS; t++) {
                bool a = false;
#pragma unroll
                for (int k = 0; k < 16; k++) {
                    m2[k] = bb2[k] * m2[k] + rb2[k] - s2[k];
                    s2[k] = (m2[k] > 1.f) ? 1.f : 0.f;
                    a = a || (s2[k] > 0.f);
                }
                unsigned a2 = __ballot_sync(0xffffffffu, a);
                float h3[16];
                if (a2) {
#pragma unroll
                    for (int k = 0; k < 16; k++) spkSh[lane + 32 * k] = s2[k];
                    __syncwarp();
#pragma unroll
                    for (int k = 0; k < 16; k++) {
                        int h = lane + 32 * k;
                        float acc = b3raw[k];
                        for (int j = 0; j < HID; j++)
                            if (spkSh[j] != 0.f) acc += W3[(size_t)h * HID + j];
                        h3[k] = fmaxf(acc, 0.f);
                    }
                    __syncwarp();
                } else {
#pragma unroll
                    for (int k = 0; k < 16; k++) h3[k] = rb3[k];
                }
                bool a3f = false;
#pragma unroll
                for (int k = 0; k < 16; k++) {
                    m3[k] = bb3[k] * m3[k] + h3[k] - s3[k];
                    s3[k] = (m3[k] > 1.f) ? 1.f : 0.f;
                    a3f = a3f || (s3[k] > 0.f);
                }
                unsigned a3 = __ballot_sync(0xffffffffu, a3f);
                if (lane == 0) g_any3A[t] = a3 ? 1u : 0u;
                if (a3) {
#pragma unroll
                    for (int k = 0; k < 16; k++) {
                        unsigned mk = __ballot_sync(0xffffffffu, s3[k] != 0.f);
                        if (lane == 0) g_maskA[t * 16 + k] = mk;
                    }
                }
            }
        }
        __threadfence();
        __syncthreads();
        if (tid == 0) atomicAdd(&g_det_done, 1);
        return;
    }

    // =================== combine blocks: one per batch =======================
    if (bid < BID_FIN) {
        const int b = bid - BID_COMB0;
        if (tid == 0) spin_until(&g_scan_done, NSCAN);
        __syncthreads();
        __threadfence();

        bool any = false;
#pragma unroll
        for (int hh = 0; hh < 2; hh++) {
            const int h = tid + hh * 256;
            const float bt = clip01(beta1[h]);
            float btL = bt;                      // beta^32 via 5 squarings
            btL = btL * btL; btL = btL * btL; btL = btL * btL;
            btL = btL * btL; btL = btL * btL;
            float M = 0.f;
#pragma unroll
            for (int c = 0; c < NCHUNK; c++) {
                const size_t idx = (size_t)(c * BATCH + b) * HID + h;
                const float lmax = g_locmax[idx];
                const float ub = ((M > 0.f) ? bt * M : btL * M) + lmax;
                any = any || (ub > 0.98f);
                M = btL * M + g_carry[idx];
            }
        }
        int flag = __syncthreads_or(any);
        if (tid == 0 && flag) atomicOr(&g_flags, 1 << b);

        if (flag && tid < 32) {
            // exact full 3-layer sequential resim (normally never taken)
            __shared__ float spkSh[HID];
            const int lane = tid;
            float m1[16], m2[16], m3[16], s1[16], s2[16], s3[16];
            float bt1[16], bt2[16], bt3[16], b2r[16], b3r[16];
#pragma unroll
            for (int k = 0; k < 16; k++) {
                int h = lane + 32 * k;
                m1[k] = m2[k] = m3[k] = 0.f;
                s1[k] = s2[k] = s3[k] = 0.f;
                bt1[k] = clip01(beta1[h]); bt2[k] = clip01(beta2[h]);
                bt3[k] = clip01(beta3[h]);
                b2r[k] = b2[h]; b3r[k] = b3[h];
            }
            for (int t = 0; t < T_STEPS; t++) {
                const int xv = x[t * BATCH + b];
                const float* ep = emb + (size_t)xv * HID;
                const float* pp = pos + (size_t)t * HID;
                bool a = false;
#pragma unroll
                for (int k = 0; k < 16; k++) {
                    int h = lane + 32 * k;
                    m1[k] = bt1[k] * m1[k] + (ep[h] + pp[h]) - s1[k];
                    s1[k] = (m1[k] > 1.f) ? 1.f : 0.f;
                    a = a || (s1[k] > 0.f);
                }
                unsigned a1 = __ballot_sync(0xffffffffu, a);
                float h2[16];
                if (a1) {
#pragma unroll
                    for (int k = 0; k < 16; k++) spkSh[lane + 32 * k] = s1[k];
                    __syncwarp();
#pragma unroll
                    for (int k = 0; k < 16; k++) {
                        int h = lane + 32 * k;
                        float acc = b2r[k];
                        for (int j = 0; j < HID; j++)
                            if (spkSh[j] != 0.f) acc += W2[(size_t)h * HID + j];
                        h2[k] = fmaxf(acc, 0.f);
                    }
                    __syncwarp();
                } else {
#pragma unroll
                    for (int k = 0; k < 16; k++) h2[k] = fmaxf(b2r[k], 0.f);
                }
                a = false;
#pragma unroll
                for (int k = 0; k < 16; k++) {
                    m2[k] = bt2[k] * m2[k] + h2[k] - s2[k];
                    s2[k] = (m2[k] > 1.f) ? 1.f : 0.f;
                    a = a || (s2[k] > 0.f);
                }
                unsigned a2 = __ballot_sync(0xffffffffu, a);
                float h3[16];
                if (a2) {
#pragma unroll
                    for (int k = 0; k < 16; k++) spkSh[lane + 32 * k] = s2[k];
                    __syncwarp();
#pragma unroll
                    for (int k = 0; k < 16; k++) {
                        int h = lane + 32 * k;
                        float acc = b3r[k];
                        for (int j = 0; j < HID; j++)
                            if (spkSh[j] != 0.f) acc += W3[(size_t)h * HID + j];
                        h3[k] = fmaxf(acc, 0.f);
                    }
                    __syncwarp();
                } else {
#pragma unroll
                    for (int k = 0; k < 16; k++) h3[k] = fmaxf(b3r[k], 0.f);
                }
                a = false;
#pragma unroll
                for (int k = 0; k < 16; k++) {
                    m3[k] = bt3[k] * m3[k] + h3[k] - s3[k];
                    s3[k] = (m3[k] > 1.f) ? 1.f : 0.f;
                    a = a || (s3[k] > 0.f);
                }
                unsigned a3 = __ballot_sync(0xffffffffu, a);
                int row = t * BATCH + b;
                if (lane == 0) g_any3B[row] = a3 ? 1u : 0u;
                if (a3) {
#pragma unroll
                    for (int k = 0; k < 16; k++) {
                        unsigned mk = __ballot_sync(0xffffffffu, s3[k] != 0.f);
                        if (lane == 0) g_maskB[row * 16 + k] = mk;
                    }
                }
            }
        }
        __threadfence();
        __syncthreads();
        if (tid == 0) atomicAdd(&g_det_done, 1);
        return;
    }

    // =================== finalizer block: fixup + counter reset ==============
    {
        if (tid == 0) {
            spin_until(&g_det_done, NDET);
            spin_until(&g_store_done, NSTORECTA);
        }
        __syncthreads();
        __threadfence();

        const int flags = g_flags;
        if (flags) {
            // rare exact path: rewrite every flagged row (bout + sparse Wout sums)
            const int mode23 = (flags >> 8) & 1;
            for (int row = 0; row < NROWS; row++) {
                const int t = row >> 3;
                const int b = row & 7;
                unsigned fl = 0;
                const unsigned* mp = nullptr;
                if ((flags >> b) & 1) { fl = g_any3B[row]; mp = &g_maskB[row * 16]; }
                else if (mode23)      { fl = g_any3A[t];   mp = &g_maskA[t * 16]; }
                if (!fl) continue;
                unsigned mloc[16];
#pragma unroll
                for (int k = 0; k < 16; k++) mloc[k] = mp[k];
                float* op = out + (size_t)row * VOCAB;
                for (int v = tid; v < VOCAB; v += 256) {
                    float o = bout[v] + mask_sum(mloc, Wout + (size_t)v * HID);
                    op[v] = o;
                }
            }
            __syncthreads();
        }

        if (tid == 0) {
            g_scan_done  = 0;
            g_det_done   = 0;
            g_flags      = 0;
            g_store_done = 0;
            __threadfence();
        }
    }
}

// ===========================================================================
extern "C" void kernel_launch(void* const* d_in, const int* in_sizes, int n_in,
                              void* d_out, int out_size)
{
    const int*   x     = (const int*)  d_in[0];
    const float* emb   = (const float*)d_in[1];
    const float* pos   = (const float*)d_in[2];
    const float* beta1 = (const float*)d_in[3];
    const float* beta2 = (const float*)d_in[4];
    const float* beta3 = (const float*)d_in[5];
    const float* W2    = (const float*)d_in[6];
    const float* b2    = (const float*)d_in[7];
    const float* W3    = (const float*)d_in[8];
    const float* b3    = (const float*)d_in[9];
    const float* Wout  = (const float*)d_in[10];
    const float* bout  = (const float*)d_in[11];
    float* out = (float*)d_out;

    fused_snn<<<GRID_TOTAL, 256>>>(x, emb, pos, beta1, beta2, beta3,
                                   W2, b2, W3, b3, Wout, bout, out);
}

// round 13
// speedup vs baseline: 1.1813x; 1.1813x over previous
#include <cuda_runtime.h>
#include <cuda_bf16.h>
#include <cstdint>

#define T_STEPS 512
#define BATCH   8
#define HID     512
#define VOCAB   32000
#define CHUNK   32
#define NCHUNK  (T_STEPS / CHUNK)          // 16

#define NSCAN      (NCHUNK * BATCH * 2)    // 256 scan blocks
#define BID_L23    NSCAN                   // 256
#define BID_COMB0  (NSCAN + 1)             // 257
#define NCOMB      BATCH                   // 8
#define BID_FIN    (BID_COMB0 + NCOMB)     // 265: finalizer / fixup block
#define BID_STORE0 (BID_FIN + 1)           // 266
#define NSTORE     2048
#define GRID_TOTAL (BID_STORE0 + NSTORE)   // 2314
#define NDET       (NCOMB + 1)

#define NROWS   (T_STEPS * BATCH)          // 4096 output rows
#define NUNITS  (NROWS * 16)               // 65536 store units (8000 B each)
#define UBATCH  8                          // units per ticket grab

// ---------------- device-global scratch (reset by finalizer each replay) ----
__device__ float    g_carry[NCHUNK * BATCH * HID];
__device__ float    g_locmax[NCHUNK * BATCH * HID];
__device__ int      g_mode23;
__device__ unsigned g_any3A[T_STEPS];
__device__ unsigned g_maskA[T_STEPS * 16];
__device__ unsigned g_any3B[T_STEPS * BATCH];
__device__ unsigned g_maskB[T_STEPS * BATCH * 16];
__device__ int      g_scan_done;
__device__ int      g_det_done;
__device__ int      g_flags;           // bit b: batch dirty; bit 8: mode23
__device__ int      g_store_done;
__device__ int      g_ticket;          // store-unit work queue head

__device__ __forceinline__ float clip01(float b) { return fminf(fmaxf(b, 0.f), 1.f); }

__device__ __forceinline__ void spin_until(volatile int* p, int target) {
    while (*p < target) __nanosleep(128);
}

__device__ __forceinline__ float mask_sum(const unsigned* __restrict__ mp,
                                          const float* __restrict__ wrow)
{
    float a = 0.f;
#pragma unroll
    for (int k = 0; k < 16; k++) {
        unsigned m = mp[k];
        while (m) {
            int j = __ffs(m) - 1;
            m &= m - 1;
            a += wrow[32 * k + j];
        }
    }
    return a;
}

// ===========================================================================
__global__ void __launch_bounds__(256, 6) fused_snn(
    const int*   __restrict__ x,
    const float* __restrict__ emb,
    const float* __restrict__ pos,
    const float* __restrict__ beta1,
    const float* __restrict__ beta2,
    const float* __restrict__ beta3,
    const float* __restrict__ W2,
    const float* __restrict__ b2,
    const float* __restrict__ W3,
    const float* __restrict__ b3,
    const float* __restrict__ Wout,
    const float* __restrict__ bout,
    float*       __restrict__ out)
{
    const int bid = blockIdx.x;
    const int tid = threadIdx.x;

    // =========== store CTAs: dynamic ticket queue over 8000-B units ==========
    if (bid >= BID_STORE0) {
        const bool has2 = tid < 244;               // 500 float4 per unit
        __shared__ int s_u0;

        int ccur = -1;
        float4 r0 = make_float4(0.f, 0.f, 0.f, 0.f);
        float4 r1 = r0;

        for (;;) {
            if (tid == 0) s_u0 = atomicAdd(&g_ticket, UBATCH);
            __syncthreads();
            const int u0 = s_u0;
            __syncthreads();
            if (u0 >= NUNITS) break;
            const int uend = (u0 + UBATCH < NUNITS) ? u0 + UBATCH : NUNITS;

            // units chunk-major: u = c*NROWS + row -> consecutive units share c
            for (int u = u0; u < uend; u++) {
                const int c   = u >> 12;           // u / NROWS
                const int row = u & (NROWS - 1);
                if (c != ccur) {
                    ccur = c;
                    const int vbase = c * 2000;
                    r0 = *reinterpret_cast<const float4*>(bout + vbase + tid * 4);
                    if (has2)
                        r1 = *reinterpret_cast<const float4*>(bout + vbase + (tid + 256) * 4);
                }
                float* op = out + (size_t)row * VOCAB + ccur * 2000;
                __stcs(reinterpret_cast<float4*>(op + tid * 4), r0);
                if (has2)
                    __stcs(reinterpret_cast<float4*>(op + (tid + 256) * 4), r1);
            }
        }

        __threadfence();          // release: stores visible before count
        __syncthreads();
        if (tid == 0) atomicAdd(&g_store_done, 1);
        return;
    }

    // =================== scan blocks: layer-1 chunk locals ===================
    if (bid < NSCAN) {
        const int c    = bid >> 4;
        const int b    = (bid >> 1) & 7;
        const int half = bid & 1;
        const int h    = half * 256 + tid;
        const int t0   = c * CHUNK;

        __shared__ unsigned xoff[CHUNK];
        if (tid < CHUNK) xoff[tid] = (unsigned)x[(t0 + tid) * BATCH + b] * (unsigned)HID;
        __syncthreads();

        const float bt = clip01(beta1[h]);
        float loc = 0.f, lmax = -1e30f;
#pragma unroll 8
        for (int i = 0; i < CHUNK; i++) {
            const float e = emb[(size_t)xoff[i] + h];
            const float p = pos[(size_t)(t0 + i) * HID + h];
            loc = bt * loc + (e + p);
            lmax = fmaxf(lmax, loc);
        }
        const size_t idx = (size_t)(c * BATCH + b) * HID + h;
        g_carry[idx]  = loc;
        g_locmax[idx] = lmax;

        __threadfence();
        __syncthreads();
        if (tid == 0) atomicAdd(&g_scan_done, 1);
        return;
    }

    // =================== layers-2/3 block (independent) ======================
    if (bid == BID_L23) {
        float lim = 0.f;
        for (int h = tid; h < HID; h += 256) {
            float be2 = clip01(beta2[h]);
            float c2  = fmaxf(b2[h], 0.f);
            float g2  = (be2 >= 1.f) ? (float)T_STEPS
                                     : (1.f - powf(be2, (float)T_STEPS)) / (1.f - be2);
            float be3 = clip01(beta3[h]);
            float c3  = fmaxf(b3[h], 0.f);
            float g3  = (be3 >= 1.f) ? (float)T_STEPS
                                     : (1.f - powf(be3, (float)T_STEPS)) / (1.f - be3);
            lim = fmaxf(lim, fmaxf(c2 * g2, c3 * g3));
        }
        int risky = __syncthreads_or(lim >= 0.98f);
        if (tid == 0) {
            g_mode23 = risky;
            if (risky) atomicOr(&g_flags, 1 << 8);
        }

        if (risky && tid < 32) {
            // exact sequential sim of layers 2/3 with constant input relu(b2)
            __shared__ float spkSh[HID];
            const int lane = tid;
            float m2[16], m3[16], s2[16], s3[16];
            float bb2[16], bb3[16], rb2[16], rb3[16], b3raw[16];
#pragma unroll
            for (int k = 0; k < 16; k++) {
                int h = lane + 32 * k;
                m2[k] = m3[k] = s2[k] = s3[k] = 0.f;
                bb2[k] = clip01(beta2[h]); bb3[k] = clip01(beta3[h]);
                rb2[k] = fmaxf(b2[h], 0.f);
                b3raw[k] = b3[h];
                rb3[k] = fmaxf(b3raw[k], 0.f);
            }
            for (int t = 0; t < T_STEPS; t++) {
                bool a = false;
#pragma unroll
                for (int k = 0; k < 16; k++) {
                    m2[k] = bb2[k] * m2[k] + rb2[k] - s2[k];
                    s2[k] = (m2[k] > 1.f) ? 1.f : 0.f;
                    a = a || (s2[k] > 0.f);
                }
                unsigned a2 = __ballot_sync(0xffffffffu, a);
                float h3[16];
                if (a2) {
#pragma unroll
                    for (int k = 0; k < 16; k++) spkSh[lane + 32 * k] = s2[k];
                    __syncwarp();
#pragma unroll
                    for (int k = 0; k < 16; k++) {
                        int h = lane + 32 * k;
                        float acc = b3raw[k];
                        for (int j = 0; j < HID; j++)
                            if (spkSh[j] != 0.f) acc += W3[(size_t)h * HID + j];
                        h3[k] = fmaxf(acc, 0.f);
                    }
                    __syncwarp();
                } else {
#pragma unroll
                    for (int k = 0; k < 16; k++) h3[k] = rb3[k];
                }
                bool a3f = false;
#pragma unroll
                for (int k = 0; k < 16; k++) {
                    m3[k] = bb3[k] * m3[k] + h3[k] - s3[k];
                    s3[k] = (m3[k] > 1.f) ? 1.f : 0.f;
                    a3f = a3f || (s3[k] > 0.f);
                }
                unsigned a3 = __ballot_sync(0xffffffffu, a3f);
                if (lane == 0) g_any3A[t] = a3 ? 1u : 0u;
                if (a3) {
#pragma unroll
                    for (int k = 0; k < 16; k++) {
                        unsigned mk = __ballot_sync(0xffffffffu, s3[k] != 0.f);
                        if (lane == 0) g_maskA[t * 16 + k] = mk;
                    }
                }
            }
        }
        __threadfence();
        __syncthreads();
        if (tid == 0) atomicAdd(&g_det_done, 1);
        return;
    }

    // =================== combine blocks: one per batch =======================
    if (bid < BID_FIN) {
        const int b = bid - BID_COMB0;
        if (tid == 0) spin_until(&g_scan_done, NSCAN);
        __syncthreads();
        __threadfence();

        bool any = false;
#pragma unroll
        for (int hh = 0; hh < 2; hh++) {
            const int h = tid + hh * 256;
            const float bt = clip01(beta1[h]);
            float btL = bt;                      // beta^32 via 5 squarings
            btL = btL * btL; btL = btL * btL; btL = btL * btL;
            btL = btL * btL; btL = btL * btL;
            float M = 0.f;
#pragma unroll
            for (int c = 0; c < NCHUNK; c++) {
                const size_t idx = (size_t)(c * BATCH + b) * HID + h;
                const float lmax = g_locmax[idx];
                const float ub = ((M > 0.f) ? bt * M : btL * M) + lmax;
                any = any || (ub > 0.98f);
                M = btL * M + g_carry[idx];
            }
        }
        int flag = __syncthreads_or(any);
        if (tid == 0 && flag) atomicOr(&g_flags, 1 << b);

        if (flag && tid < 32) {
            // exact full 3-layer sequential resim (normally never taken)
            __shared__ float spkSh[HID];
            const int lane = tid;
            float m1[16], m2[16], m3[16], s1[16], s2[16], s3[16];
            float bt1[16], bt2[16], bt3[16], b2r[16], b3r[16];
#pragma unroll
            for (int k = 0; k < 16; k++) {
                int h = lane + 32 * k;
                m1[k] = m2[k] = m3[k] = 0.f;
                s1[k] = s2[k] = s3[k] = 0.f;
                bt1[k] = clip01(beta1[h]); bt2[k] = clip01(beta2[h]);
                bt3[k] = clip01(beta3[h]);
                b2r[k] = b2[h]; b3r[k] = b3[h];
            }
            for (int t = 0; t < T_STEPS; t++) {
                const int xv = x[t * BATCH + b];
                const float* ep = emb + (size_t)xv * HID;
                const float* pp = pos + (size_t)t * HID;
                bool a = false;
#pragma unroll
                for (int k = 0; k < 16; k++) {
                    int h = lane + 32 * k;
                    m1[k] = bt1[k] * m1[k] + (ep[h] + pp[h]) - s1[k];
                    s1[k] = (m1[k] > 1.f) ? 1.f : 0.f;
                    a = a || (s1[k] > 0.f);
                }
                unsigned a1 = __ballot_sync(0xffffffffu, a);
                float h2[16];
                if (a1) {
#pragma unroll
                    for (int k = 0; k < 16; k++) spkSh[lane + 32 * k] = s1[k];
                    __syncwarp();
#pragma unroll
                    for (int k = 0; k < 16; k++) {
                        int h = lane + 32 * k;
                        float acc = b2r[k];
                        for (int j = 0; j < HID; j++)
                            if (spkSh[j] != 0.f) acc += W2[(size_t)h * HID + j];
                        h2[k] = fmaxf(acc, 0.f);
                    }
                    __syncwarp();
                } else {
#pragma unroll
                    for (int k = 0; k < 16; k++) h2[k] = fmaxf(b2r[k], 0.f);
                }
                a = false;
#pragma unroll
                for (int k = 0; k < 16; k++) {
                    m2[k] = bt2[k] * m2[k] + h2[k] - s2[k];
                    s2[k] = (m2[k] > 1.f) ? 1.f : 0.f;
                    a = a || (s2[k] > 0.f);
                }
                unsigned a2 = __ballot_sync(0xffffffffu, a);
                float h3[16];
                if (a2) {
#pragma unroll
                    for (int k = 0; k < 16; k++) spkSh[lane + 32 * k] = s2[k];
                    __syncwarp();
#pragma unroll
                    for (int k = 0; k < 16; k++) {
                        int h = lane + 32 * k;
                        float acc = b3r[k];
                        for (int j = 0; j < HID; j++)
                            if (spkSh[j] != 0.f) acc += W3[(size_t)h * HID + j];
                        h3[k] = fmaxf(acc, 0.f);
                    }
                    __syncwarp();
                } else {
#pragma unroll
                    for (int k = 0; k < 16; k++) h3[k] = fmaxf(b3r[k], 0.f);
                }
                a = false;
#pragma unroll
                for (int k = 0; k < 16; k++) {
                    m3[k] = bt3[k] * m3[k] + h3[k] - s3[k];
                    s3[k] = (m3[k] > 1.f) ? 1.f : 0.f;
                    a = a || (s3[k] > 0.f);
                }
                unsigned a3 = __ballot_sync(0xffffffffu, a);
                int row = t * BATCH + b;
                if (lane == 0) g_any3B[row] = a3 ? 1u : 0u;
                if (a3) {
#pragma unroll
                    for (int k = 0; k < 16; k++) {
                        unsigned mk = __ballot_sync(0xffffffffu, s3[k] != 0.f);
                        if (lane == 0) g_maskB[row * 16 + k] = mk;
                    }
                }
            }
        }
        __threadfence();
        __syncthreads();
        if (tid == 0) atomicAdd(&g_det_done, 1);
        return;
    }

    // =================== finalizer block: fixup + counter reset ==============
    {
        if (tid == 0) {
            spin_until(&g_det_done, NDET);
            spin_until(&g_store_done, NSTORE);
        }
        __syncthreads();
        __threadfence();

        const int flags = g_flags;
        if (flags) {
            // rare exact path: rewrite every flagged row (bout + sparse Wout sums)
            const int mode23 = (flags >> 8) & 1;
            for (int row = 0; row < NROWS; row++) {
                const int t = row >> 3;
                const int b = row & 7;
                unsigned fl = 0;
                const unsigned* mp = nullptr;
                if ((flags >> b) & 1) { fl = g_any3B[row]; mp = &g_maskB[row * 16]; }
                else if (mode23)      { fl = g_any3A[t];   mp = &g_maskA[t * 16]; }
                if (!fl) continue;
                unsigned mloc[16];
#pragma unroll
                for (int k = 0; k < 16; k++) mloc[k] = mp[k];
                float* op = out + (size_t)row * VOCAB;
                for (int v = tid; v < VOCAB; v += 256) {
                    float o = bout[v] + mask_sum(mloc, Wout + (size_t)v * HID);
                    op[v] = o;
                }
            }
            __syncthreads();
        }

        if (tid == 0) {
            g_scan_done  = 0;
            g_det_done   = 0;
            g_flags      = 0;
            g_store_done = 0;
            g_ticket     = 0;
            __threadfence();
        }
    }
}

// ===========================================================================
extern "C" void kernel_launch(void* const* d_in, const int* in_sizes, int n_in,
                              void* d_out, int out_size)
{
    const int*   x     = (const int*)  d_in[0];
    const float* emb   = (const float*)d_in[1];
    const float* pos   = (const float*)d_in[2];
    const float* beta1 = (const float*)d_in[3];
    const float* beta2 = (const float*)d_in[4];
    const float* beta3 = (const float*)d_in[5];
    const float* W2    = (const float*)d_in[6];
    const float* b2    = (const float*)d_in[7];
    const float* W3    = (const float*)d_in[8];
    const float* b3    = (const float*)d_in[9];
    const float* Wout  = (const float*)d_in[10];
    const float* bout  = (const float*)d_in[11];
    float* out = (float*)d_out;

    fused_snn<<<GRID_TOTAL, 256>>>(x, emb, pos, beta1, beta2, beta3,
                                   W2, b2, W3, b3, Wout, bout, out);
}